// round 11
// baseline (speedup 1.0000x reference)
#include <cuda_runtime.h>
#include <cuda_bf16.h>
#include <math.h>

#define B_      8
#define IN_CH   512
#define OUT_CH  256
#define HW      64
#define OH      129
#define SPW     67
#define SP      4736

// ---------------- scratch ----------------
__device__ float g_style[B_ * IN_CH];
__device__ float g_demod[B_ * OUT_CH];
__device__ float g_wsqT[IN_CH * OUT_CH];
__device__ __nv_bfloat16 g_Wh[(size_t)B_ * 9 * OUT_CH * IN_CH];  // [b][tap][o][i]
__device__ __nv_bfloat16 g_Wl[(size_t)B_ * 9 * OUT_CH * IN_CH];
__device__ __nv_bfloat16 g_Xh[(size_t)B_ * SP * IN_CH];          // [b][n][i]
__device__ __nv_bfloat16 g_Xl[(size_t)B_ * SP * IN_CH];
__device__ float g_out1[(size_t)B_ * OUT_CH * OH * OH];

// ---------------- ptx helpers ----------------
__device__ __forceinline__ unsigned su32(const void* p) {
    unsigned a;
    asm("{ .reg .u64 t; cvta.to.shared.u64 t, %1; cvt.u32.u64 %0, t; }" : "=r"(a) : "l"(p));
    return a;
}
__device__ __forceinline__ void cpa16(unsigned dst, const void* src) {
    asm volatile("cp.async.cg.shared.global [%0], [%1], 16;" :: "r"(dst), "l"(src));
}
__device__ __forceinline__ unsigned swz(unsigned x) { return x ^ ((x >> 3) & 0x70); }

__device__ __forceinline__ void ldsm4(unsigned r[4], unsigned addr) {
    asm volatile("ldmatrix.sync.aligned.m8n8.x4.shared.b16 {%0,%1,%2,%3}, [%4];"
        : "=r"(r[0]), "=r"(r[1]), "=r"(r[2]), "=r"(r[3]) : "r"(addr));
}
__device__ __forceinline__ void mma16816(float c[4], const unsigned a[4],
                                         unsigned b0, unsigned b1) {
    asm volatile(
        "mma.sync.aligned.m16n8k16.row.col.f32.bf16.bf16.f32 "
        "{%0,%1,%2,%3}, {%4,%5,%6,%7}, {%8,%9}, {%0,%1,%2,%3};"
        : "+f"(c[0]), "+f"(c[1]), "+f"(c[2]), "+f"(c[3])
        : "r"(a[0]), "r"(a[1]), "r"(a[2]), "r"(a[3]), "r"(b0), "r"(b1));
}

// ---------------- 1) style + wsq fused ----------------
__global__ void __launch_bounds__(512) style_wsq_kernel(const float* __restrict__ w,
                                                        const float* __restrict__ aw,
                                                        const float* __restrict__ bias,
                                                        const float* __restrict__ cw) {
    if (blockIdx.x < B_) {
        int b = blockIdx.x;
        int i = threadIdx.x;
        __shared__ float ws[IN_CH];
        ws[i] = w[b * IN_CH + i];
        __syncthreads();
        const float* ar = aw + (size_t)i * IN_CH;
        float s = 0.f;
#pragma unroll 8
        for (int l = 0; l < IN_CH; ++l) s = fmaf(ws[l], ar[l], s);
        g_style[b * IN_CH + i] = s * 0.04419417382415922f + bias[i];
    } else {
        int t = (blockIdx.x - B_) * 512 + threadIdx.x;
        int o = t & (OUT_CH - 1);
        int i = t >> 8;
        const float* p = cw + ((size_t)o * IN_CH + i) * 9;
        float s = 0.f;
#pragma unroll
        for (int k = 0; k < 9; ++k) s = fmaf(p[k], p[k], s);
        g_wsqT[i * OUT_CH + o] = s;
    }
}

// ---------------- 2) demod ----------------
__global__ void demod_kernel() {
    int b = blockIdx.x;
    int o = threadIdx.x;
    __shared__ float s2[IN_CH];
    for (int l = threadIdx.x; l < IN_CH; l += 256) {
        float v = g_style[b * IN_CH + l];
        s2[l] = v * v;
    }
    __syncthreads();
    float acc = 0.f;
#pragma unroll 4
    for (int i = 0; i < IN_CH; ++i) acc = fmaf(s2[i], g_wsqT[i * OUT_CH + o], acc);
    g_demod[b * OUT_CH + o] = rsqrtf(acc * (1.f / 4608.f) + 1e-8f);
}

// ---------------- 3) wsplit ----------------
__global__ void wsplit_kernel(const float* __restrict__ cw) {
    int b = blockIdx.y;
    int e = blockIdx.x * 256 + threadIdx.x;
    int i = e & 511;
    int o = (e >> 9) & 255;
    int t = e >> 17;
    float m = cw[((size_t)o * IN_CH + i) * 9 + t] * 0.014731391274719739f
            * g_style[b * IN_CH + i] * g_demod[b * OUT_CH + o];
    __nv_bfloat16 h = __float2bfloat16(m);
    __nv_bfloat16 l = __float2bfloat16(m - __bfloat162float(h));
    size_t idx = (((size_t)b * 9 + t) * OUT_CH + o) * IN_CH + i;
    g_Wh[idx] = h;
    g_Wl[idx] = l;
}

// ---------------- 4) xsplit (+ built-in padding zero; xzero removed) ----------------
__global__ void xsplit_kernel(const float* __restrict__ x) {
    int icb = blockIdx.x;
    int b   = blockIdx.z;
    int t   = threadIdx.x;

    if (blockIdx.y == 64) {
        // zero exactly the padding cells read for valid outputs:
        // row sy=0 (n 0..66), cols sx in {0,65,66} for sy=1..64, row sy=65 (n 4355..4421)
        for (int j = t; j < 326 * 64; j += 256) {
            int ni = j >> 6;          // 0..325
            int ic = j & 63;
            int n;
            if (ni < 67) n = ni;
            else if (ni < 259) {
                int r = (ni - 67) / 3 + 1;
                int c = (ni - 67) % 3;
                n = r * 67 + (c == 0 ? 0 : (c == 1 ? 65 : 66));
            } else n = 4355 + (ni - 259);
            size_t idx = ((size_t)b * SP + n) * IN_CH + icb * 64 + ic;
            g_Xh[idx] = __float2bfloat16(0.f);
            g_Xl[idx] = __float2bfloat16(0.f);
        }
        return;
    }

    __shared__ float sm[64][65];
    int y  = blockIdx.y;
    int xr = t & 63, ics = t >> 6;
#pragma unroll
    for (int r = 0; r < 16; ++r) {
        int ic = ics * 16 + r;
        sm[ic][xr] = x[(((size_t)b * IN_CH + icb * 64 + ic) * HW + y) * HW + xr];
    }
    __syncthreads();
    int icw = t & 63, xs = t >> 6;
#pragma unroll
    for (int r = 0; r < 16; ++r) {
        int xc = xs + 4 * r;
        float v = sm[icw][xc];
        __nv_bfloat16 h = __float2bfloat16(v);
        __nv_bfloat16 l = __float2bfloat16(v - __bfloat162float(h));
        size_t idx = ((size_t)b * SP + (y + 1) * SPW + (xc + 1)) * IN_CH + icb * 64 + icw;
        g_Xh[idx] = h;
        g_Xl[idx] = l;
    }
}

// ---------------- 4b) pixel (128,128): single-tap GEMV in fp32 ----------------
// out1[b,o,128,128] = sum_i Wmod[b,tap=8,o,i] * x[b,i,63,63]
__global__ void pix_kernel(const float* __restrict__ x, const float* __restrict__ cw) {
    int b = blockIdx.x;
    int o = threadIdx.x;                 // 256
    __shared__ float xs[IN_CH];
    for (int i = threadIdx.x; i < IN_CH; i += 256)
        xs[i] = x[((size_t)(b * IN_CH + i)) * HW * HW + 63 * HW + 63]
              * g_style[b * IN_CH + i];
    __syncthreads();
    float s = 0.f;
#pragma unroll 4
    for (int i = 0; i < IN_CH; ++i)
        s = fmaf(cw[((size_t)o * IN_CH + i) * 9 + 8], xs[i], s);
    s *= 0.014731391274719739f * g_demod[b * OUT_CH + o];
    g_out1[(((size_t)(b * OUT_CH + o)) * OH + 128) * OH + 128] = s;
}

// ---------------- 5) fused HMMA GEMM (R9 internals; grid 17, LPT parity order) ----
#define BN      256
#define WROWS   264
#define STAGES  3

template <int RY, int RX>
__device__ __forceinline__ void mm_body(unsigned char* dsm, int mblk, int b) {
    constexpr int NG    = (RY == 0) ? 2 : 1;
    constexpr int NKX   = (RX == 0) ? 2 : 1;
    constexpr int C     = 3 * NG * 8;
    constexpr int Py    = 65 - RY, Px = 65 - RX;
    constexpr int ABYTES = NKX * 16384;
    constexpr int BBYTES = WROWS * 128;
    constexpr int STAGE  = ABYTES + BBYTES;

    const unsigned sbase = (su32(dsm) + 1023) & ~1023u;
    const int n0 = blockIdx.x * BN;      // 17 blocks cover n < 4352; (128,128) via pix

    const int tid  = threadIdx.x;
    const int wid  = tid >> 5;
    const int lane = tid & 31;
    const int wm   = wid >> 3;           // 0..1 -> m offset 64
    const int wn   = wid & 7;            // 0..7 -> n offset 32

    auto issue = [&](int c) {
        const int pass = c / (NG * 8);
        const int rem  = c - pass * (NG * 8);
        const int g    = rem >> 3;
        const int q    = rem & 7;
        const __nv_bfloat16* Wp = (pass == 2) ? g_Wl : g_Wh;
        const __nv_bfloat16* Xp = (pass == 1) ? g_Xl : g_Xh;
        const int kh   = (RY == 0) ? 2 * g : 1;
        const int tofb = (1 - (kh >> 1)) * SPW;
        const unsigned stg = sbase + (unsigned)(c % STAGES) * STAGE;
#pragma unroll
        for (int j = 0; j < NKX; ++j) {
            const int kw = (RX == 0) ? 2 * j : 1;
            const __nv_bfloat16* As =
                Wp + (((size_t)b * 9 + kh * 3 + kw) * OUT_CH + mblk * 128) * IN_CH + q * 64;
#pragma unroll
            for (int u = 0; u < 2; ++u) {
                int idx = tid + 512 * u;
                int row = idx >> 3, ch = idx & 7;
                cpa16(stg + j * 16384 + swz(row * 128 + ch * 16),
                      As + (size_t)row * IN_CH + ch * 8);
            }
        }
        const __nv_bfloat16* Bs = Xp + ((size_t)b * SP + n0 + tofb) * IN_CH + q * 64;
#pragma unroll
        for (int u = 0; u < 5; ++u) {
            int idx = tid + 512 * u;
            if (idx < WROWS * 8) {
                int row = idx >> 3, ch = idx & 7;
                cpa16(stg + ABYTES + swz(row * 128 + ch * 16),
                      Bs + (size_t)row * IN_CH + ch * 8);
            }
        }
        asm volatile("cp.async.commit_group;");
    };

    float acc[4][4][4];
#pragma unroll
    for (int mi = 0; mi < 4; ++mi)
#pragma unroll
        for (int ni = 0; ni < 4; ++ni)
#pragma unroll
            for (int e = 0; e < 4; ++e) acc[mi][ni][e] = 0.f;

    issue(0);
    issue(1);

    for (int c = 0; c < C; ++c) {
        if (c + 2 < C) {
            issue(c + 2);
            asm volatile("cp.async.wait_group 2;");
        } else if (c + 2 == C) {
            asm volatile("cp.async.wait_group 1;");
        } else {
            asm volatile("cp.async.wait_group 0;");
        }
        __syncthreads();

        const unsigned As = sbase + (unsigned)(c % STAGES) * STAGE;
        const unsigned Bs = As + ABYTES;
#pragma unroll
        for (int ks = 0; ks < 4; ++ks) {
            const int chsel = ks * 2 + (lane >> 4);
#pragma unroll
            for (int j = 0; j < NKX; ++j) {
                unsigned af[4][4];
#pragma unroll
                for (int mi = 0; mi < 4; ++mi) {
                    int row = wm * 64 + mi * 16 + (lane & 15);
                    ldsm4(af[mi], As + j * 16384 + swz(row * 128 + chsel * 16));
                }
                const int dt = (RX == 0) ? (1 - j) : 1;
                unsigned bm[2][4];
#pragma unroll
                for (int nj = 0; nj < 2; ++nj) {
                    int row = dt + wn * 32 + nj * 16 + (lane & 15);
                    ldsm4(bm[nj], Bs + swz(row * 128 + chsel * 16));
                }
#pragma unroll
                for (int mi = 0; mi < 4; ++mi)
#pragma unroll
                    for (int ni = 0; ni < 4; ++ni) {
                        unsigned b0 = bm[ni >> 1][ni & 1];
                        unsigned b1 = bm[ni >> 1][(ni & 1) + 2];
                        mma16816(acc[mi][ni], af[mi], b0, b1);
                    }
            }
        }
        __syncthreads();
    }

#pragma unroll
    for (int mi = 0; mi < 4; ++mi) {
        const int m = mblk * 128 + wm * 64 + mi * 16 + (lane >> 2);
#pragma unroll
        for (int ni = 0; ni < 4; ++ni) {
            const int nA = n0 + wn * 32 + ni * 8 + 2 * (lane & 3);
#pragma unroll
            for (int e = 0; e < 2; ++e) {
                const int n  = nA + e;
                const int py = n / SPW;
                const int px = n - py * SPW;
                if (py < Py && px < Px) {
                    size_t o0 = (((size_t)(b * OUT_CH + m)) * OH + 2 * py + RY) * OH
                              + 2 * px + RX;
                    g_out1[o0] = acc[mi][ni][e];
                    g_out1[o0 + (size_t)8 * OH * OH] = acc[mi][ni][2 + e];
                }
            }
        }
    }
}

__global__ void __launch_bounds__(512) mm_fused() {
    extern __shared__ unsigned char dsm[];
    const int p    = blockIdx.z;        // LPT order: heavy parities first
    const int b    = blockIdx.y >> 1;
    const int mblk = blockIdx.y & 1;
    switch (p) {
        case 0:  mm_body<0, 0>(dsm, mblk, b); break;
        case 1:  mm_body<0, 1>(dsm, mblk, b); break;
        case 2:  mm_body<1, 0>(dsm, mblk, b); break;
        default: mm_body<1, 1>(dsm, mblk, b); break;
    }
}

// ---------------- 6) blur: 512 threads, 32x16 tiles ----------------
__global__ void __launch_bounds__(512) blur_kernel(float* __restrict__ out) {
    int bo = blockIdx.z;
    int y0 = blockIdx.y * 16;
    int x0 = blockIdx.x * 32;
    __shared__ float sm[19][36];
    const float* src = g_out1 + (size_t)bo * OH * OH;
    int tid = threadIdx.x;
    for (int idx = tid; idx < 19 * 35; idx += 512) {
        int r = idx / 35, c = idx % 35;
        int gy = y0 - 1 + r, gx = x0 - 1 + c;
        sm[r][c] = ((unsigned)gy < OH && (unsigned)gx < OH) ? src[gy * OH + gx] : 0.f;
    }
    __syncthreads();
    int ly = tid >> 5, lx = tid & 31;
    const float cf[4] = {1.f, 3.f, 3.f, 1.f};
    float acc = 0.f;
#pragma unroll
    for (int u = 0; u < 4; ++u)
#pragma unroll
        for (int v = 0; v < 4; ++v)
            acc = fmaf(cf[u] * cf[v], sm[ly + u][lx + v], acc);
    out[(size_t)bo * 128 * 128 + (y0 + ly) * 128 + (x0 + lx)] = acc * (1.f / 16.f);
}

// ---------------- launch ----------------
extern "C" void kernel_launch(void* const* d_in, const int* in_sizes, int n_in,
                              void* d_out, int out_size) {
    const float* input = (const float*)d_in[0];
    const float* w     = (const float*)d_in[1];
    const float* aw    = (const float*)d_in[2];
    const float* bias  = (const float*)d_in[3];
    const float* cw    = (const float*)d_in[4];
    float* out = (float*)d_out;

    const int S2 = STAGES * (2 * 16384 + WROWS * 128) + 2048;   // 201728
    cudaFuncSetAttribute(mm_fused, cudaFuncAttributeMaxDynamicSharedMemorySize, S2);

    style_wsq_kernel<<<B_ + (IN_CH * OUT_CH) / 512, 512>>>(w, aw, bias, cw);
    demod_kernel<<<B_, OUT_CH>>>();
    wsplit_kernel<<<dim3((9 * IN_CH * OUT_CH) / 256, B_), 256>>>(cw);
    xsplit_kernel<<<dim3(8, 65, B_), 256>>>(input);
    pix_kernel<<<B_, OUT_CH>>>(input, cw);
    mm_fused<<<dim3(17, 16, 4), 512, S2>>>();
    blur_kernel<<<dim3(4, 8, B_ * OUT_CH), 512>>>(out);
}

// round 12
// speedup vs baseline: 1.3349x; 1.3349x over previous
#include <cuda_runtime.h>
#include <cuda_fp16.h>
#include <math.h>

#define B_      8
#define IN_CH   512
#define OUT_CH  256
#define HW      64
#define OH      129
#define SPW     67
#define SP      4736

// ---------------- scratch ----------------
__device__ float g_style[B_ * IN_CH];
__device__ float g_demod[B_ * OUT_CH];
__device__ float g_wsqT[IN_CH * OUT_CH];
__device__ __half g_Wh[(size_t)B_ * 9 * OUT_CH * IN_CH];   // [b][tap][o][i] fp16 hi
__device__ __half g_Wl[(size_t)B_ * 9 * OUT_CH * IN_CH];   // fp16 lo (residual)
__device__ __half g_X [(size_t)B_ * SP * IN_CH];           // [b][n][i] fp16 (single)
__device__ float g_out1[(size_t)B_ * OUT_CH * OH * OH];

// ---------------- ptx helpers ----------------
__device__ __forceinline__ unsigned su32(const void* p) {
    unsigned a;
    asm("{ .reg .u64 t; cvta.to.shared.u64 t, %1; cvt.u32.u64 %0, t; }" : "=r"(a) : "l"(p));
    return a;
}
__device__ __forceinline__ void cpa16(unsigned dst, const void* src) {
    asm volatile("cp.async.cg.shared.global [%0], [%1], 16;" :: "r"(dst), "l"(src));
}
__device__ __forceinline__ unsigned swz(unsigned x) { return x ^ ((x >> 3) & 0x70); }

__device__ __forceinline__ void ldsm4(unsigned r[4], unsigned addr) {
    asm volatile("ldmatrix.sync.aligned.m8n8.x4.shared.b16 {%0,%1,%2,%3}, [%4];"
        : "=r"(r[0]), "=r"(r[1]), "=r"(r[2]), "=r"(r[3]) : "r"(addr));
}
__device__ __forceinline__ void mma16816(float c[4], const unsigned a[4],
                                         unsigned b0, unsigned b1) {
    asm volatile(
        "mma.sync.aligned.m16n8k16.row.col.f32.f16.f16.f32 "
        "{%0,%1,%2,%3}, {%4,%5,%6,%7}, {%8,%9}, {%0,%1,%2,%3};"
        : "+f"(c[0]), "+f"(c[1]), "+f"(c[2]), "+f"(c[3])
        : "r"(a[0]), "r"(a[1]), "r"(a[2]), "r"(a[3]), "r"(b0), "r"(b1));
}

// ---------------- 0) zero-fill padded X ----------------
__global__ void xzero_kernel() {
    size_t t = (size_t)blockIdx.x * 256 + threadIdx.x;   // uint4 index
    ((uint4*)g_X)[t] = make_uint4(0, 0, 0, 0);
}

// ---------------- 1) style + wsq fused ----------------
__global__ void __launch_bounds__(512) style_wsq_kernel(const float* __restrict__ w,
                                                        const float* __restrict__ aw,
                                                        const float* __restrict__ bias,
                                                        const float* __restrict__ cw) {
    if (blockIdx.x < B_) {
        int b = blockIdx.x;
        int i = threadIdx.x;
        __shared__ float ws[IN_CH];
        ws[i] = w[b * IN_CH + i];
        __syncthreads();
        const float* ar = aw + (size_t)i * IN_CH;
        float s = 0.f;
#pragma unroll 8
        for (int l = 0; l < IN_CH; ++l) s = fmaf(ws[l], ar[l], s);
        g_style[b * IN_CH + i] = s * 0.04419417382415922f + bias[i];
    } else {
        int t = (blockIdx.x - B_) * 512 + threadIdx.x;
        int o = t & (OUT_CH - 1);
        int i = t >> 8;
        const float* p = cw + ((size_t)o * IN_CH + i) * 9;
        float s = 0.f;
#pragma unroll
        for (int k = 0; k < 9; ++k) s = fmaf(p[k], p[k], s);
        g_wsqT[i * OUT_CH + o] = s;
    }
}

// ---------------- 2) demod ----------------
__global__ void demod_kernel() {
    int b = blockIdx.x;
    int o = threadIdx.x;
    __shared__ float s2[IN_CH];
    for (int l = threadIdx.x; l < IN_CH; l += 256) {
        float v = g_style[b * IN_CH + l];
        s2[l] = v * v;
    }
    __syncthreads();
    float acc = 0.f;
#pragma unroll 4
    for (int i = 0; i < IN_CH; ++i) acc = fmaf(s2[i], g_wsqT[i * OUT_CH + o], acc);
    g_demod[b * OUT_CH + o] = rsqrtf(acc * (1.f / 4608.f) + 1e-8f);
}

// ---------------- 3) wsplit: fp16 hi/lo ----------------
__global__ void wsplit_kernel(const float* __restrict__ cw) {
    int b = blockIdx.y;
    int e = blockIdx.x * 256 + threadIdx.x;
    int i = e & 511;
    int o = (e >> 9) & 255;
    int t = e >> 17;
    float m = cw[((size_t)o * IN_CH + i) * 9 + t] * 0.014731391274719739f
            * g_style[b * IN_CH + i] * g_demod[b * OUT_CH + o];
    __half h = __float2half_rn(m);
    __half l = __float2half_rn(m - __half2float(h));
    size_t idx = (((size_t)b * 9 + t) * OUT_CH + o) * IN_CH + i;
    g_Wh[idx] = h;
    g_Wl[idx] = l;
}

// ---------------- 4) xsplit: transpose + pad, single fp16 ----------------
__global__ void xsplit_kernel(const float* __restrict__ x) {
    __shared__ float sm[64][65];
    int icb = blockIdx.x;
    int y   = blockIdx.y;
    int b   = blockIdx.z;
    int t   = threadIdx.x;
    int xr  = t & 63, ics = t >> 6;
#pragma unroll
    for (int r = 0; r < 16; ++r) {
        int ic = ics * 16 + r;
        sm[ic][xr] = x[(((size_t)b * IN_CH + icb * 64 + ic) * HW + y) * HW + xr];
    }
    __syncthreads();
    int icw = t & 63, xs = t >> 6;
#pragma unroll
    for (int r = 0; r < 16; ++r) {
        int xc = xs + 4 * r;
        size_t idx = ((size_t)b * SP + (y + 1) * SPW + (xc + 1)) * IN_CH + icb * 64 + icw;
        g_X[idx] = __float2half_rn(sm[icw][xc]);
    }
}

// ---------------- 5) fused HMMA GEMM: fp16 2-pass folded into A tiles ----------------
// chunk = (kh-group g, ic-chunk q). One B window (fp16 X) serves NKX kw-taps x 2 halves.
#define BN      256
#define WROWS   264
#define STAGES  2

template <int RY, int RX>
__device__ __forceinline__ void mm_body(unsigned char* dsm, int mblk, int b) {
    constexpr int NG    = (RY == 0) ? 2 : 1;
    constexpr int NKX   = (RX == 0) ? 2 : 1;
    constexpr int NJ    = NKX * 2;            // (kw-tap, hi/lo) A tiles per chunk
    constexpr int C     = NG * 8;             // chunks (BK=64)
    constexpr int Py    = 65 - RY, Px = 65 - RX;
    constexpr int SPAN  = (Py - 1) * SPW + Px;
    constexpr int ABYTES = NJ * 16384;
    constexpr int BBYTES = WROWS * 128;       // 264 rows x 64 half
    constexpr int STAGE  = ABYTES + BBYTES;

    const unsigned sbase = (su32(dsm) + 1023) & ~1023u;

    const int n0 = blockIdx.x * BN;
    if (n0 >= SPAN) return;

    const int tid  = threadIdx.x;
    const int wid  = tid >> 5;
    const int lane = tid & 31;
    const int wm   = wid >> 3;          // 0..1 -> m offset 64
    const int wn   = wid & 7;           // 0..7 -> n offset 32

    auto issue = [&](int c) {
        const int g = c >> 3;
        const int q = c & 7;
        const int kh   = (RY == 0) ? 2 * g : 1;
        const int tofb = (1 - (kh >> 1)) * SPW;
        const unsigned stg = sbase + (unsigned)(c % STAGES) * STAGE;
#pragma unroll
        for (int j = 0; j < NJ; ++j) {
            const int kw = (RX == 0) ? 2 * (j >> 1) : 1;
            const __half* Wp = (j & 1) ? g_Wl : g_Wh;
            const __half* As =
                Wp + (((size_t)b * 9 + kh * 3 + kw) * OUT_CH + mblk * 128) * IN_CH + q * 64;
#pragma unroll
            for (int u = 0; u < 2; ++u) {
                int idx = tid + 512 * u;           // 1024 ops: 128 rows x 8 chunks
                int row = idx >> 3, ch = idx & 7;
                cpa16(stg + j * 16384 + swz(row * 128 + ch * 16),
                      As + (size_t)row * IN_CH + ch * 8);
            }
        }
        const __half* Bs = g_X + ((size_t)b * SP + n0 + tofb) * IN_CH + q * 64;
#pragma unroll
        for (int u = 0; u < 5; ++u) {
            int idx = tid + 512 * u;               // 2112 ops
            if (idx < WROWS * 8) {
                int row = idx >> 3, ch = idx & 7;
                cpa16(stg + ABYTES + swz(row * 128 + ch * 16),
                      Bs + (size_t)row * IN_CH + ch * 8);
            }
        }
        asm volatile("cp.async.commit_group;");
    };

    float acc[4][4][4];
#pragma unroll
    for (int mi = 0; mi < 4; ++mi)
#pragma unroll
        for (int ni = 0; ni < 4; ++ni)
#pragma unroll
            for (int e = 0; e < 4; ++e) acc[mi][ni][e] = 0.f;

    issue(0);

    for (int c = 0; c < C; ++c) {
        if (c + 1 < C) {
            issue(c + 1);
            asm volatile("cp.async.wait_group 1;");
        } else {
            asm volatile("cp.async.wait_group 0;");
        }
        __syncthreads();

        const unsigned As = sbase + (unsigned)(c % STAGES) * STAGE;
        const unsigned Bs = As + ABYTES;
#pragma unroll
        for (int ks = 0; ks < 4; ++ks) {
            const int chsel = ks * 2 + (lane >> 4);
#pragma unroll
            for (int j = 0; j < NJ; ++j) {
                unsigned af[4][4];
#pragma unroll
                for (int mi = 0; mi < 4; ++mi) {
                    int row = wm * 64 + mi * 16 + (lane & 15);
                    ldsm4(af[mi], As + j * 16384 + swz(row * 128 + chsel * 16));
                }
                const int dt = (RX == 0) ? (1 - (j >> 1)) : 1;   // B row shift for this tap
                unsigned bm[2][4];
#pragma unroll
                for (int nj = 0; nj < 2; ++nj) {
                    int row = dt + wn * 32 + nj * 16 + (lane & 15);
                    ldsm4(bm[nj], Bs + swz(row * 128 + chsel * 16));
                }
#pragma unroll
                for (int mi = 0; mi < 4; ++mi)
#pragma unroll
                    for (int ni = 0; ni < 4; ++ni) {
                        unsigned b0 = bm[ni >> 1][ni & 1];
                        unsigned b1 = bm[ni >> 1][(ni & 1) + 2];
                        mma16816(acc[mi][ni], af[mi], b0, b1);
                    }
            }
        }
        __syncthreads();
    }

    // ---- epilogue: direct strided stores ----
#pragma unroll
    for (int mi = 0; mi < 4; ++mi) {
        const int m = mblk * 128 + wm * 64 + mi * 16 + (lane >> 2);
#pragma unroll
        for (int ni = 0; ni < 4; ++ni) {
            const int nA = n0 + wn * 32 + ni * 8 + 2 * (lane & 3);
#pragma unroll
            for (int e = 0; e < 2; ++e) {
                const int n  = nA + e;
                const int py = n / SPW;
                const int px = n - py * SPW;
                if (py < Py && px < Px) {
                    size_t o0 = (((size_t)(b * OUT_CH + m)) * OH + 2 * py + RY) * OH
                              + 2 * px + RX;
                    g_out1[o0] = acc[mi][ni][e];
                    g_out1[o0 + (size_t)8 * OH * OH] = acc[mi][ni][2 + e];
                }
            }
        }
    }
}

__global__ void __launch_bounds__(512) mm_fused() {
    extern __shared__ unsigned char dsm[];
    const int p    = blockIdx.y >> 1;
    const int mblk = blockIdx.y & 1;
    const int b    = blockIdx.z;
    switch (p) {
        case 0:  mm_body<0, 0>(dsm, mblk, b); break;
        case 1:  mm_body<0, 1>(dsm, mblk, b); break;
        case 2:  mm_body<1, 0>(dsm, mblk, b); break;
        default: mm_body<1, 1>(dsm, mblk, b); break;
    }
}

// ---------------- 6) blur ----------------
__global__ void blur_kernel(float* __restrict__ out) {
    int bo = blockIdx.z;
    int y0 = blockIdx.y * 16;
    int x0 = blockIdx.x * 16;
    __shared__ float sm[19][20];
    const float* src = g_out1 + (size_t)bo * OH * OH;
    int tid = threadIdx.x;
    for (int idx = tid; idx < 19 * 19; idx += 256) {
        int r = idx / 19, c = idx % 19;
        int gy = y0 - 1 + r, gx = x0 - 1 + c;
        sm[r][c] = ((unsigned)gy < OH && (unsigned)gx < OH) ? src[gy * OH + gx] : 0.f;
    }
    __syncthreads();
    int ly = tid >> 4, lx = tid & 15;
    const float cf[4] = {1.f, 3.f, 3.f, 1.f};
    float acc = 0.f;
#pragma unroll
    for (int u = 0; u < 4; ++u)
#pragma unroll
        for (int v = 0; v < 4; ++v)
            acc = fmaf(cf[u] * cf[v], sm[ly + u][lx + v], acc);
    out[(size_t)bo * 128 * 128 + (y0 + ly) * 128 + (x0 + lx)] = acc * (1.f / 16.f);
}

// ---------------- launch ----------------
extern "C" void kernel_launch(void* const* d_in, const int* in_sizes, int n_in,
                              void* d_out, int out_size) {
    const float* input = (const float*)d_in[0];
    const float* w     = (const float*)d_in[1];
    const float* aw    = (const float*)d_in[2];
    const float* bias  = (const float*)d_in[3];
    const float* cw    = (const float*)d_in[4];
    float* out = (float*)d_out;

    // max stage: NJ=4 -> 2*(4*16384 + 264*128) + 2048 = 200704 bytes
    const int S2 = STAGES * (4 * 16384 + WROWS * 128) + 2048;
    cudaFuncSetAttribute(mm_fused, cudaFuncAttributeMaxDynamicSharedMemorySize, S2);

    xzero_kernel<<<(int)(((size_t)B_ * SP * IN_CH / 8) / 256), 256>>>();
    style_wsq_kernel<<<B_ + (IN_CH * OUT_CH) / 512, 512>>>(w, aw, bias, cw);
    demod_kernel<<<B_, OUT_CH>>>();
    wsplit_kernel<<<dim3((9 * IN_CH * OUT_CH) / 256, B_), 256>>>(cw);
    xsplit_kernel<<<dim3(8, 64, B_), 256>>>(input);
    mm_fused<<<dim3(18, 8, B_), 512, S2>>>();
    blur_kernel<<<dim3(8, 8, B_ * OUT_CH), 256>>>(out);
}

// round 13
// speedup vs baseline: 1.7516x; 1.3121x over previous
#include <cuda_runtime.h>
#include <cuda_fp16.h>
#include <math.h>

#define B_      8
#define IN_CH   512
#define OUT_CH  256
#define HW      64
#define OH      129
#define SPW     67
#define SP      4736

// ---------------- scratch ----------------
__device__ float g_style[B_ * IN_CH];
__device__ float g_demod[B_ * OUT_CH];
__device__ float g_wsqT[IN_CH * OUT_CH];
__device__ __half g_W[(size_t)B_ * 9 * OUT_CH * IN_CH];    // [b][tap][o][i] fp16
__device__ __half g_X[(size_t)B_ * SP * IN_CH];            // [b][n][i] fp16
__device__ float g_out1[(size_t)B_ * OUT_CH * OH * OH];

// ---------------- ptx helpers ----------------
__device__ __forceinline__ unsigned su32(const void* p) {
    unsigned a;
    asm("{ .reg .u64 t; cvta.to.shared.u64 t, %1; cvt.u32.u64 %0, t; }" : "=r"(a) : "l"(p));
    return a;
}
__device__ __forceinline__ void cpa16(unsigned dst, const void* src) {
    asm volatile("cp.async.cg.shared.global [%0], [%1], 16;" :: "r"(dst), "l"(src));
}
__device__ __forceinline__ unsigned swz(unsigned x) { return x ^ ((x >> 3) & 0x70); }

__device__ __forceinline__ void ldsm4(unsigned r[4], unsigned addr) {
    asm volatile("ldmatrix.sync.aligned.m8n8.x4.shared.b16 {%0,%1,%2,%3}, [%4];"
        : "=r"(r[0]), "=r"(r[1]), "=r"(r[2]), "=r"(r[3]) : "r"(addr));
}
__device__ __forceinline__ void mma16816(float c[4], const unsigned a[4],
                                         unsigned b0, unsigned b1) {
    asm volatile(
        "mma.sync.aligned.m16n8k16.row.col.f32.f16.f16.f32 "
        "{%0,%1,%2,%3}, {%4,%5,%6,%7}, {%8,%9}, {%0,%1,%2,%3};"
        : "+f"(c[0]), "+f"(c[1]), "+f"(c[2]), "+f"(c[3])
        : "r"(a[0]), "r"(a[1]), "r"(a[2]), "r"(a[3]), "r"(b0), "r"(b1));
}

// ---------------- 0) zero-fill padded X ----------------
__global__ void xzero_kernel() {
    size_t t = (size_t)blockIdx.x * 256 + threadIdx.x;   // uint4 index
    ((uint4*)g_X)[t] = make_uint4(0, 0, 0, 0);
}

// ---------------- 1) style + wsq fused ----------------
__global__ void __launch_bounds__(512) style_wsq_kernel(const float* __restrict__ w,
                                                        const float* __restrict__ aw,
                                                        const float* __restrict__ bias,
                                                        const float* __restrict__ cw) {
    if (blockIdx.x < B_) {
        int b = blockIdx.x;
        int i = threadIdx.x;
        __shared__ float ws[IN_CH];
        ws[i] = w[b * IN_CH + i];
        __syncthreads();
        const float* ar = aw + (size_t)i * IN_CH;
        float s = 0.f;
#pragma unroll 8
        for (int l = 0; l < IN_CH; ++l) s = fmaf(ws[l], ar[l], s);
        g_style[b * IN_CH + i] = s * 0.04419417382415922f + bias[i];
    } else {
        int t = (blockIdx.x - B_) * 512 + threadIdx.x;
        int o = t & (OUT_CH - 1);
        int i = t >> 8;
        const float* p = cw + ((size_t)o * IN_CH + i) * 9;
        float s = 0.f;
#pragma unroll
        for (int k = 0; k < 9; ++k) s = fmaf(p[k], p[k], s);
        g_wsqT[i * OUT_CH + o] = s;
    }
}

// ---------------- 2) demod ----------------
__global__ void demod_kernel() {
    int b = blockIdx.x;
    int o = threadIdx.x;
    __shared__ float s2[IN_CH];
    for (int l = threadIdx.x; l < IN_CH; l += 256) {
        float v = g_style[b * IN_CH + l];
        s2[l] = v * v;
    }
    __syncthreads();
    float acc = 0.f;
#pragma unroll 4
    for (int i = 0; i < IN_CH; ++i) acc = fmaf(s2[i], g_wsqT[i * OUT_CH + o], acc);
    g_demod[b * OUT_CH + o] = rsqrtf(acc * (1.f / 4608.f) + 1e-8f);
}

// ---------------- 3) wsplit: single fp16 ----------------
__global__ void wsplit_kernel(const float* __restrict__ cw) {
    int b = blockIdx.y;
    int e = blockIdx.x * 256 + threadIdx.x;
    int i = e & 511;
    int o = (e >> 9) & 255;
    int t = e >> 17;
    float m = cw[((size_t)o * IN_CH + i) * 9 + t] * 0.014731391274719739f
            * g_style[b * IN_CH + i] * g_demod[b * OUT_CH + o];
    g_W[(((size_t)b * 9 + t) * OUT_CH + o) * IN_CH + i] = __float2half_rn(m);
}

// ---------------- 4) xsplit: transpose + pad, single fp16 ----------------
__global__ void xsplit_kernel(const float* __restrict__ x) {
    __shared__ float sm[64][65];
    int icb = blockIdx.x;
    int y   = blockIdx.y;
    int b   = blockIdx.z;
    int t   = threadIdx.x;
    int xr  = t & 63, ics = t >> 6;
#pragma unroll
    for (int r = 0; r < 16; ++r) {
        int ic = ics * 16 + r;
        sm[ic][xr] = x[(((size_t)b * IN_CH + icb * 64 + ic) * HW + y) * HW + xr];
    }
    __syncthreads();
    int icw = t & 63, xs = t >> 6;
#pragma unroll
    for (int r = 0; r < 16; ++r) {
        int xc = xs + 4 * r;
        size_t idx = ((size_t)b * SP + (y + 1) * SPW + (xc + 1)) * IN_CH + icb * 64 + icw;
        g_X[idx] = __float2half_rn(sm[icw][xc]);
    }
}

// ---------------- 5) fused HMMA GEMM: single fp16 pass ----------------
// chunk = (kh-group g, ic-chunk q). One B window serves NKX kw-taps.
#define BN      256
#define WROWS   264
#define STAGES  2

template <int RY, int RX>
__device__ __forceinline__ void mm_body(unsigned char* dsm, int mblk, int b) {
    constexpr int NG    = (RY == 0) ? 2 : 1;
    constexpr int NKX   = (RX == 0) ? 2 : 1;
    constexpr int NJ    = NKX;                // kw-tap A tiles per chunk
    constexpr int C     = NG * 8;             // chunks (BK=64)
    constexpr int Py    = 65 - RY, Px = 65 - RX;
    constexpr int SPAN  = (Py - 1) * SPW + Px;
    constexpr int ABYTES = NJ * 16384;
    constexpr int BBYTES = WROWS * 128;
    constexpr int STAGE  = ABYTES + BBYTES;

    const unsigned sbase = (su32(dsm) + 1023) & ~1023u;

    const int n0 = blockIdx.x * BN;
    if (n0 >= SPAN) return;

    const int tid  = threadIdx.x;
    const int wid  = tid >> 5;
    const int lane = tid & 31;
    const int wm   = wid >> 3;          // 0..1 -> m offset 64
    const int wn   = wid & 7;           // 0..7 -> n offset 32

    auto issue = [&](int c) {
        const int g = c >> 3;
        const int q = c & 7;
        const int kh   = (RY == 0) ? 2 * g : 1;
        const int tofb = (1 - (kh >> 1)) * SPW;
        const unsigned stg = sbase + (unsigned)(c % STAGES) * STAGE;
#pragma unroll
        for (int j = 0; j < NJ; ++j) {
            const int kw = (RX == 0) ? 2 * j : 1;
            const __half* As =
                g_W + (((size_t)b * 9 + kh * 3 + kw) * OUT_CH + mblk * 128) * IN_CH + q * 64;
#pragma unroll
            for (int u = 0; u < 2; ++u) {
                int idx = tid + 512 * u;           // 1024 ops: 128 rows x 8 chunks
                int row = idx >> 3, ch = idx & 7;
                cpa16(stg + j * 16384 + swz(row * 128 + ch * 16),
                      As + (size_t)row * IN_CH + ch * 8);
            }
        }
        const __half* Bs = g_X + ((size_t)b * SP + n0 + tofb) * IN_CH + q * 64;
#pragma unroll
        for (int u = 0; u < 5; ++u) {
            int idx = tid + 512 * u;               // 2112 ops
            if (idx < WROWS * 8) {
                int row = idx >> 3, ch = idx & 7;
                cpa16(stg + ABYTES + swz(row * 128 + ch * 16),
                      Bs + (size_t)row * IN_CH + ch * 8);
            }
        }
        asm volatile("cp.async.commit_group;");
    };

    float acc[4][4][4];
#pragma unroll
    for (int mi = 0; mi < 4; ++mi)
#pragma unroll
        for (int ni = 0; ni < 4; ++ni)
#pragma unroll
            for (int e = 0; e < 4; ++e) acc[mi][ni][e] = 0.f;

    issue(0);

    for (int c = 0; c < C; ++c) {
        if (c + 1 < C) {
            issue(c + 1);
            asm volatile("cp.async.wait_group 1;");
        } else {
            asm volatile("cp.async.wait_group 0;");
        }
        __syncthreads();

        const unsigned As = sbase + (unsigned)(c % STAGES) * STAGE;
        const unsigned Bs = As + ABYTES;
#pragma unroll
        for (int ks = 0; ks < 4; ++ks) {
            const int chsel = ks * 2 + (lane >> 4);
#pragma unroll
            for (int j = 0; j < NJ; ++j) {
                unsigned af[4][4];
#pragma unroll
                for (int mi = 0; mi < 4; ++mi) {
                    int row = wm * 64 + mi * 16 + (lane & 15);
                    ldsm4(af[mi], As + j * 16384 + swz(row * 128 + chsel * 16));
                }
                const int dt = (RX == 0) ? (1 - j) : 1;   // B row shift for this tap
                unsigned bm[2][4];
#pragma unroll
                for (int nj = 0; nj < 2; ++nj) {
                    int row = dt + wn * 32 + nj * 16 + (lane & 15);
                    ldsm4(bm[nj], Bs + swz(row * 128 + chsel * 16));
                }
#pragma unroll
                for (int mi = 0; mi < 4; ++mi)
#pragma unroll
                    for (int ni = 0; ni < 4; ++ni) {
                        unsigned b0 = bm[ni >> 1][ni & 1];
                        unsigned b1 = bm[ni >> 1][(ni & 1) + 2];
                        mma16816(acc[mi][ni], af[mi], b0, b1);
                    }
            }
        }
        __syncthreads();
    }

    // ---- epilogue: direct strided stores ----
#pragma unroll
    for (int mi = 0; mi < 4; ++mi) {
        const int m = mblk * 128 + wm * 64 + mi * 16 + (lane >> 2);
#pragma unroll
        for (int ni = 0; ni < 4; ++ni) {
            const int nA = n0 + wn * 32 + ni * 8 + 2 * (lane & 3);
#pragma unroll
            for (int e = 0; e < 2; ++e) {
                const int n  = nA + e;
                const int py = n / SPW;
                const int px = n - py * SPW;
                if (py < Py && px < Px) {
                    size_t o0 = (((size_t)(b * OUT_CH + m)) * OH + 2 * py + RY) * OH
                              + 2 * px + RX;
                    g_out1[o0] = acc[mi][ni][e];
                    g_out1[o0 + (size_t)8 * OH * OH] = acc[mi][ni][2 + e];
                }
            }
        }
    }
}

__global__ void __launch_bounds__(512) mm_fused() {
    extern __shared__ unsigned char dsm[];
    const int p    = blockIdx.y >> 1;
    const int mblk = blockIdx.y & 1;
    const int b    = blockIdx.z;
    switch (p) {
        case 0:  mm_body<0, 0>(dsm, mblk, b); break;
        case 1:  mm_body<0, 1>(dsm, mblk, b); break;
        case 2:  mm_body<1, 0>(dsm, mblk, b); break;
        default: mm_body<1, 1>(dsm, mblk, b); break;
    }
}

// ---------------- 6) blur ----------------
__global__ void blur_kernel(float* __restrict__ out) {
    int bo = blockIdx.z;
    int y0 = blockIdx.y * 16;
    int x0 = blockIdx.x * 16;
    __shared__ float sm[19][20];
    const float* src = g_out1 + (size_t)bo * OH * OH;
    int tid = threadIdx.x;
    for (int idx = tid; idx < 19 * 19; idx += 256) {
        int r = idx / 19, c = idx % 19;
        int gy = y0 - 1 + r, gx = x0 - 1 + c;
        sm[r][c] = ((unsigned)gy < OH && (unsigned)gx < OH) ? src[gy * OH + gx] : 0.f;
    }
    __syncthreads();
    int ly = tid >> 4, lx = tid & 15;
    const float cf[4] = {1.f, 3.f, 3.f, 1.f};
    float acc = 0.f;
#pragma unroll
    for (int u = 0; u < 4; ++u)
#pragma unroll
        for (int v = 0; v < 4; ++v)
            acc = fmaf(cf[u] * cf[v], sm[ly + u][lx + v], acc);
    out[(size_t)bo * 128 * 128 + (y0 + ly) * 128 + (x0 + lx)] = acc * (1.f / 16.f);
}

// ---------------- launch ----------------
extern "C" void kernel_launch(void* const* d_in, const int* in_sizes, int n_in,
                              void* d_out, int out_size) {
    const float* input = (const float*)d_in[0];
    const float* w     = (const float*)d_in[1];
    const float* aw    = (const float*)d_in[2];
    const float* bias  = (const float*)d_in[3];
    const float* cw    = (const float*)d_in[4];
    float* out = (float*)d_out;

    // max stage: NJ=2 -> 2*(2*16384 + 264*128) + 2048 = 135168 bytes
    const int S2 = STAGES * (2 * 16384 + WROWS * 128) + 2048;
    cudaFuncSetAttribute(mm_fused, cudaFuncAttributeMaxDynamicSharedMemorySize, S2);

    xzero_kernel<<<(int)(((size_t)B_ * SP * IN_CH / 8) / 256), 256>>>();
    style_wsq_kernel<<<B_ + (IN_CH * OUT_CH) / 512, 512>>>(w, aw, bias, cw);
    demod_kernel<<<B_, OUT_CH>>>();
    wsplit_kernel<<<dim3((9 * IN_CH * OUT_CH) / 256, B_), 256>>>(cw);
    xsplit_kernel<<<dim3(8, 64, B_), 256>>>(input);
    mm_fused<<<dim3(18, 8, B_), 512, S2>>>();
    blur_kernel<<<dim3(8, 8, B_ * OUT_CH), 256>>>(out);
}

// round 14
// speedup vs baseline: 1.9255x; 1.0993x over previous
#include <cuda_runtime.h>
#include <cuda_fp16.h>
#include <math.h>

#define B_      8
#define IN_CH   512
#define OUT_CH  256
#define HW      64
#define OH      129
#define SPW     67
#define SP      4736
#define PLANE   4290               // 65 rows x 66 halves per (p,b,o)

// ---------------- scratch ----------------
__device__ float g_style[B_ * IN_CH];
__device__ float g_demod[B_ * OUT_CH];
__device__ float g_wsqT[IN_CH * OUT_CH];
__device__ __half g_W[(size_t)B_ * 9 * OUT_CH * IN_CH];    // [b][tap][o][i] fp16
__device__ __half g_X[(size_t)B_ * SP * IN_CH];            // [b][n][i] fp16
__device__ __half g_out1h[(size_t)4 * B_ * OUT_CH * PLANE];// [p][b][o][py][px]

// ---------------- ptx helpers ----------------
__device__ __forceinline__ unsigned su32(const void* p) {
    unsigned a;
    asm("{ .reg .u64 t; cvta.to.shared.u64 t, %1; cvt.u32.u64 %0, t; }" : "=r"(a) : "l"(p));
    return a;
}
__device__ __forceinline__ void cpa16(unsigned dst, const void* src) {
    asm volatile("cp.async.cg.shared.global [%0], [%1], 16;" :: "r"(dst), "l"(src));
}
__device__ __forceinline__ unsigned swz(unsigned x) { return x ^ ((x >> 3) & 0x70); }

__device__ __forceinline__ void ldsm4(unsigned r[4], unsigned addr) {
    asm volatile("ldmatrix.sync.aligned.m8n8.x4.shared.b16 {%0,%1,%2,%3}, [%4];"
        : "=r"(r[0]), "=r"(r[1]), "=r"(r[2]), "=r"(r[3]) : "r"(addr));
}
__device__ __forceinline__ void mma16816(float c[4], const unsigned a[4],
                                         unsigned b0, unsigned b1) {
    asm volatile(
        "mma.sync.aligned.m16n8k16.row.col.f32.f16.f16.f32 "
        "{%0,%1,%2,%3}, {%4,%5,%6,%7}, {%8,%9}, {%0,%1,%2,%3};"
        : "+f"(c[0]), "+f"(c[1]), "+f"(c[2]), "+f"(c[3])
        : "r"(a[0]), "r"(a[1]), "r"(a[2]), "r"(a[3]), "r"(b0), "r"(b1));
}

// ---------------- 0) zero-fill padded X ----------------
__global__ void xzero_kernel() {
    size_t t = (size_t)blockIdx.x * 256 + threadIdx.x;   // uint4 index
    ((uint4*)g_X)[t] = make_uint4(0, 0, 0, 0);
}

// ---------------- 1) style + wsq fused ----------------
__global__ void __launch_bounds__(512) style_wsq_kernel(const float* __restrict__ w,
                                                        const float* __restrict__ aw,
                                                        const float* __restrict__ bias,
                                                        const float* __restrict__ cw) {
    if (blockIdx.x < B_) {
        int b = blockIdx.x;
        int i = threadIdx.x;
        __shared__ float ws[IN_CH];
        ws[i] = w[b * IN_CH + i];
        __syncthreads();
        const float* ar = aw + (size_t)i * IN_CH;
        float s = 0.f;
#pragma unroll 8
        for (int l = 0; l < IN_CH; ++l) s = fmaf(ws[l], ar[l], s);
        g_style[b * IN_CH + i] = s * 0.04419417382415922f + bias[i];
    } else {
        int t = (blockIdx.x - B_) * 512 + threadIdx.x;
        int o = t & (OUT_CH - 1);
        int i = t >> 8;
        const float* p = cw + ((size_t)o * IN_CH + i) * 9;
        float s = 0.f;
#pragma unroll
        for (int k = 0; k < 9; ++k) s = fmaf(p[k], p[k], s);
        g_wsqT[i * OUT_CH + o] = s;
    }
}

// ---------------- 2) demod ----------------
__global__ void demod_kernel() {
    int b = blockIdx.x;
    int o = threadIdx.x;
    __shared__ float s2[IN_CH];
    for (int l = threadIdx.x; l < IN_CH; l += 256) {
        float v = g_style[b * IN_CH + l];
        s2[l] = v * v;
    }
    __syncthreads();
    float acc = 0.f;
#pragma unroll 4
    for (int i = 0; i < IN_CH; ++i) acc = fmaf(s2[i], g_wsqT[i * OUT_CH + o], acc);
    g_demod[b * OUT_CH + o] = rsqrtf(acc * (1.f / 4608.f) + 1e-8f);
}

// ---------------- 3) wsplit: single fp16 ----------------
__global__ void wsplit_kernel(const float* __restrict__ cw) {
    int b = blockIdx.y;
    int e = blockIdx.x * 256 + threadIdx.x;
    int i = e & 511;
    int o = (e >> 9) & 255;
    int t = e >> 17;
    float m = cw[((size_t)o * IN_CH + i) * 9 + t] * 0.014731391274719739f
            * g_style[b * IN_CH + i] * g_demod[b * OUT_CH + o];
    g_W[(((size_t)b * 9 + t) * OUT_CH + o) * IN_CH + i] = __float2half_rn(m);
}

// ---------------- 4) xsplit: transpose + pad, single fp16 ----------------
__global__ void xsplit_kernel(const float* __restrict__ x) {
    __shared__ float sm[64][65];
    int icb = blockIdx.x;
    int y   = blockIdx.y;
    int b   = blockIdx.z;
    int t   = threadIdx.x;
    int xr  = t & 63, ics = t >> 6;
#pragma unroll
    for (int r = 0; r < 16; ++r) {
        int ic = ics * 16 + r;
        sm[ic][xr] = x[(((size_t)b * IN_CH + icb * 64 + ic) * HW + y) * HW + xr];
    }
    __syncthreads();
    int icw = t & 63, xs = t >> 6;
#pragma unroll
    for (int r = 0; r < 16; ++r) {
        int xc = xs + 4 * r;
        size_t idx = ((size_t)b * SP + (y + 1) * SPW + (xc + 1)) * IN_CH + icb * 64 + icw;
        g_X[idx] = __float2half_rn(sm[icw][xc]);
    }
}

// ---------------- 5) fused HMMA GEMM, fp16 planar epilogue ----------------
#define BN      256
#define WROWS   264
#define STAGES  2
#define TST     258                 // smem transpose row stride (halves)

template <int RY, int RX>
__device__ __forceinline__ void mm_body(unsigned char* dsm, int mblk, int b) {
    constexpr int NG    = (RY == 0) ? 2 : 1;
    constexpr int NKX   = (RX == 0) ? 2 : 1;
    constexpr int NJ    = NKX;
    constexpr int C     = NG * 8;
    constexpr int Py    = 65 - RY, Px = 65 - RX;
    constexpr int SPAN  = (Py - 1) * SPW + Px;
    constexpr int ABYTES = NJ * 16384;
    constexpr int BBYTES = WROWS * 128;
    constexpr int STAGE  = ABYTES + BBYTES;

    const unsigned sbase = (su32(dsm) + 1023) & ~1023u;

    const int n0 = blockIdx.x * BN;
    if (n0 >= SPAN) return;

    const int tid  = threadIdx.x;
    const int wid  = tid >> 5;
    const int lane = tid & 31;
    const int wm   = wid >> 3;
    const int wn   = wid & 7;

    auto issue = [&](int c) {
        const int g = c >> 3;
        const int q = c & 7;
        const int kh   = (RY == 0) ? 2 * g : 1;
        const int tofb = (1 - (kh >> 1)) * SPW;
        const unsigned stg = sbase + (unsigned)(c % STAGES) * STAGE;
#pragma unroll
        for (int j = 0; j < NJ; ++j) {
            const int kw = (RX == 0) ? 2 * j : 1;
            const __half* As =
                g_W + (((size_t)b * 9 + kh * 3 + kw) * OUT_CH + mblk * 128) * IN_CH + q * 64;
#pragma unroll
            for (int u = 0; u < 2; ++u) {
                int idx = tid + 512 * u;
                int row = idx >> 3, ch = idx & 7;
                cpa16(stg + j * 16384 + swz(row * 128 + ch * 16),
                      As + (size_t)row * IN_CH + ch * 8);
            }
        }
        const __half* Bs = g_X + ((size_t)b * SP + n0 + tofb) * IN_CH + q * 64;
#pragma unroll
        for (int u = 0; u < 5; ++u) {
            int idx = tid + 512 * u;
            if (idx < WROWS * 8) {
                int row = idx >> 3, ch = idx & 7;
                cpa16(stg + ABYTES + swz(row * 128 + ch * 16),
                      Bs + (size_t)row * IN_CH + ch * 8);
            }
        }
        asm volatile("cp.async.commit_group;");
    };

    float acc[4][4][4];
#pragma unroll
    for (int mi = 0; mi < 4; ++mi)
#pragma unroll
        for (int ni = 0; ni < 4; ++ni)
#pragma unroll
            for (int e = 0; e < 4; ++e) acc[mi][ni][e] = 0.f;

    issue(0);

    for (int c = 0; c < C; ++c) {
        if (c + 1 < C) {
            issue(c + 1);
            asm volatile("cp.async.wait_group 1;");
        } else {
            asm volatile("cp.async.wait_group 0;");
        }
        __syncthreads();

        const unsigned As = sbase + (unsigned)(c % STAGES) * STAGE;
        const unsigned Bs = As + ABYTES;
#pragma unroll
        for (int ks = 0; ks < 4; ++ks) {
            const int chsel = ks * 2 + (lane >> 4);
#pragma unroll
            for (int j = 0; j < NJ; ++j) {
                unsigned af[4][4];
#pragma unroll
                for (int mi = 0; mi < 4; ++mi) {
                    int row = wm * 64 + mi * 16 + (lane & 15);
                    ldsm4(af[mi], As + j * 16384 + swz(row * 128 + chsel * 16));
                }
                const int dt = (RX == 0) ? (1 - j) : 1;
                unsigned bm[2][4];
#pragma unroll
                for (int nj = 0; nj < 2; ++nj) {
                    int row = dt + wn * 32 + nj * 16 + (lane & 15);
                    ldsm4(bm[nj], Bs + swz(row * 128 + chsel * 16));
                }
#pragma unroll
                for (int mi = 0; mi < 4; ++mi)
#pragma unroll
                    for (int ni = 0; ni < 4; ++ni) {
                        unsigned b0 = bm[ni >> 1][ni & 1];
                        unsigned b1 = bm[ni >> 1][(ni & 1) + 2];
                        mma16816(acc[mi][ni], af[mi], b0, b1);
                    }
            }
        }
        __syncthreads();
    }

    // ---- epilogue: smem transpose -> coalesced fp16 planar stores ----
    __half* T = (__half*)dsm;            // [128][TST]; loop's last sync protects reuse
#pragma unroll
    for (int mi = 0; mi < 4; ++mi) {
        const int ml = wm * 64 + mi * 16 + (lane >> 2);
#pragma unroll
        for (int ni = 0; ni < 4; ++ni) {
            const int col = wn * 32 + ni * 8 + 2 * (lane & 3);
            *(__half2*)&T[ml * TST + col] =
                __floats2half2_rn(acc[mi][ni][0], acc[mi][ni][1]);
            *(__half2*)&T[(ml + 8) * TST + col] =
                __floats2half2_rn(acc[mi][ni][2], acc[mi][ni][3]);
        }
    }
    __syncthreads();

    __half* plane = g_out1h
        + (((size_t)(RY * 2 + RX) * B_ + b) * OUT_CH + mblk * 128) * PLANE;
    const int c0 = tid & 127;
    const int rg = tid >> 7;
#pragma unroll 4
    for (int k = 0; k < 32; ++k) {
        const int row = rg + 4 * k;
#pragma unroll
        for (int hh = 0; hh < 2; ++hh) {
            const int col = c0 + 128 * hh;
            const int n  = n0 + col;
            const int py = n / SPW;
            const int px = n - py * SPW;
            if (py < Py && px < Px)
                plane[(size_t)row * PLANE + py * 66 + px] = T[row * TST + col];
        }
    }
}

__global__ void __launch_bounds__(512) mm_fused() {
    extern __shared__ unsigned char dsm[];
    const int p    = blockIdx.y >> 1;
    const int mblk = blockIdx.y & 1;
    const int b    = blockIdx.z;
    switch (p) {
        case 0:  mm_body<0, 0>(dsm, mblk, b); break;
        case 1:  mm_body<0, 1>(dsm, mblk, b); break;
        case 2:  mm_body<1, 0>(dsm, mblk, b); break;
        default: mm_body<1, 1>(dsm, mblk, b); break;
    }
}

// ---------------- 6) blur: gather from fp16 parity planes ----------------
__global__ void blur_kernel(float* __restrict__ out) {
    int bo = blockIdx.z;                 // b*256 + o
    int y0 = blockIdx.y * 16;
    int x0 = blockIdx.x * 16;
    __shared__ float sm[19][20];
    int tid = threadIdx.x;
    const __half* base = g_out1h + (size_t)bo * PLANE;   // plane p at + p*B_*OUT_CH*PLANE
    const size_t pstride = (size_t)B_ * OUT_CH * PLANE;
    for (int idx = tid; idx < 19 * 19; idx += 256) {
        int r = idx / 19, c = idx % 19;
        int Y = y0 - 1 + r, X = x0 - 1 + c;
        float v = 0.f;
        if ((unsigned)Y < 129u && (unsigned)X < 129u) {
            int p = (Y & 1) * 2 + (X & 1);
            v = __half2float(base[p * pstride + (Y >> 1) * 66 + (X >> 1)]);
        }
        sm[r][c] = v;
    }
    __syncthreads();
    int ly = tid >> 4, lx = tid & 15;
    const float cf[4] = {1.f, 3.f, 3.f, 1.f};
    float acc = 0.f;
#pragma unroll
    for (int u = 0; u < 4; ++u)
#pragma unroll
        for (int v = 0; v < 4; ++v)
            acc = fmaf(cf[u] * cf[v], sm[ly + u][lx + v], acc);
    out[(size_t)bo * 128 * 128 + (y0 + ly) * 128 + (x0 + lx)] = acc * (1.f / 16.f);
}

// ---------------- launch ----------------
extern "C" void kernel_launch(void* const* d_in, const int* in_sizes, int n_in,
                              void* d_out, int out_size) {
    const float* input = (const float*)d_in[0];
    const float* w     = (const float*)d_in[1];
    const float* aw    = (const float*)d_in[2];
    const float* bias  = (const float*)d_in[3];
    const float* cw    = (const float*)d_in[4];
    float* out = (float*)d_out;

    // max stage: NJ=2 -> 2*(2*16384 + 264*128) + 2048 = 135168 bytes
    // (also covers the 128x258 fp16 transpose buffer = 66048 bytes)
    const int S2 = STAGES * (2 * 16384 + WROWS * 128) + 2048;
    cudaFuncSetAttribute(mm_fused, cudaFuncAttributeMaxDynamicSharedMemorySize, S2);

    xzero_kernel<<<(int)(((size_t)B_ * SP * IN_CH / 8) / 256), 256>>>();
    style_wsq_kernel<<<B_ + (IN_CH * OUT_CH) / 512, 512>>>(w, aw, bias, cw);
    demod_kernel<<<B_, OUT_CH>>>();
    wsplit_kernel<<<dim3((9 * IN_CH * OUT_CH) / 256, B_), 256>>>(cw);
    xsplit_kernel<<<dim3(8, 64, B_), 256>>>(input);
    mm_fused<<<dim3(18, 8, B_), 512, S2>>>();
    blur_kernel<<<dim3(8, 8, B_ * OUT_CH), 256>>>(out);
}